// round 2
// baseline (speedup 1.0000x reference)
#include <cuda_runtime.h>
#include <math.h>

#define Nn   50000
#define Ee   800000
#define Ff   32
#define NINVc 128
#define NLc  4
#define Hc   64
#define Gc   2048
#define EPSf 1e-6f

// ---------------- device scratch (no allocs allowed) ----------------
__device__ float  g_edge_in[Ee*5];
__device__ float  g_u[Ee*3];
__device__ int    g_src[Ee];
__device__ int    g_dst[Ee];
__device__ float  g_s[Nn*Ff];
__device__ float  g_v[Nn*Ff*3];
__device__ float4 g_acc[Nn*Ff];       // {ms, mv0, mv1, mv2} accumulators
__device__ float  g_invden[Nn];
__device__ float  g_cnt[Nn];
__device__ float  g_xg[Gc*NINVc];
__device__ float  g_gcnt[Gc];
__device__ float  g_xgp[Gc*NINVc];
__device__ float  g_z1[Gc*NINVc];
__device__ float  g_mean1[NINVc], g_rstd1[NINVc], g_mean2[NINVc], g_rstd2[NINVc];

__device__ __forceinline__ float elu1(float x) { return x > 0.f ? x : expm1f(x); }

// ---------------- zero kernels ----------------
__global__ void k_zero_node_graph() {
    int i = blockIdx.x*blockDim.x + threadIdx.x;
    if (i < Nn) g_cnt[i] = 0.f;
    else if (i < Nn + Gc) g_gcnt[i - Nn] = 0.f;
    else if (i < Nn + Gc + Gc*NINVc) g_xg[i - Nn - Gc] = 0.f;
}
__global__ void k_zero_acc() {
    int i = blockIdx.x*blockDim.x + threadIdx.x;
    if (i < Nn*Ff) g_acc[i] = make_float4(0.f,0.f,0.f,0.f);
}

// ---------------- preprocessing ----------------
__global__ void k_edge_prep(const float* __restrict__ pos,
                            const int* __restrict__ ei,
                            const float* __restrict__ eattr) {
    int e = blockIdx.x*blockDim.x + threadIdx.x;
    if (e >= Ee) return;
    int src = ei[e];
    int dst = ei[Ee + e];
    float dx = pos[dst*3+0] - pos[src*3+0];
    float dy = pos[dst*3+1] - pos[src*3+1];
    float dz = pos[dst*3+2] - pos[src*3+2];
    float d  = sqrtf(dx*dx + dy*dy + dz*dz + EPSf);
    float inv = 1.0f/d;
    g_edge_in[e*5+0] = d;
    g_edge_in[e*5+1] = eattr[e*4+0];
    g_edge_in[e*5+2] = eattr[e*4+1];
    g_edge_in[e*5+3] = eattr[e*4+2];
    g_edge_in[e*5+4] = eattr[e*4+3];
    g_u[e*3+0] = dx*inv;
    g_u[e*3+1] = dy*inv;
    g_u[e*3+2] = dz*inv;
    g_src[e] = src;
    g_dst[e] = dst;
    atomicAdd(&g_cnt[dst], 1.f);
}
__global__ void k_gcnt(const int* __restrict__ batch) {
    int n = blockIdx.x*blockDim.x + threadIdx.x;
    if (n < Nn) atomicAdd(&g_gcnt[batch[n]], 1.f);
}
__global__ void k_invden() {
    int n = blockIdx.x*blockDim.x + threadIdx.x;
    if (n < Nn) g_invden[n] = 1.f / fmaxf(g_cnt[n], 1.f);
}

// ---------------- embedding ----------------
__global__ void k_embed(const float* __restrict__ x, const float* __restrict__ pos,
                        const float* __restrict__ W_es, const float* __restrict__ b_es,
                        const float* __restrict__ W_ev) {
    int idx = blockIdx.x*blockDim.x + threadIdx.x;
    if (idx >= Nn*Ff) return;
    int n = idx >> 5, f = idx & 31;
    const float* xr = x + n*5;
    float s = b_es[f], ev = 0.f;
    #pragma unroll
    for (int k = 0; k < 5; k++) {
        float xv = xr[k];
        s  += xv * W_es[k*Ff + f];
        ev += xv * W_ev[k*Ff + f];
    }
    g_s[idx] = s;
    float p0 = pos[n*3+0], p1 = pos[n*3+1], p2 = pos[n*3+2];
    g_v[idx*3+0] = ev*p0;
    g_v[idx*3+1] = ev*p1;
    g_v[idx*3+2] = ev*p2;
}

// ---------------- per-layer fused: edge MLP (tiled GEMM) + message + scatter ----------------
// shared layout (floats): w1s[320] b1s[64] w2s[6144] b2s[96] eins[320] us[192]
//                         srcs[64](int) dsts[64](int) hT[64*68] hsh[64*96]
#define MSG_SMEM_FLOATS (320+64+6144+96+320+192+64+64+64*68+64*96)
__global__ void k_msg(const float* __restrict__ W1, const float* __restrict__ b1,
                      const float* __restrict__ W2, const float* __restrict__ b2) {
    extern __shared__ float sm[];
    float* w1s  = sm;                 // 5x64
    float* b1s  = w1s + 320;          // 64
    float* w2s  = b1s + 64;           // 64x96
    float* b2s  = w2s + 6144;         // 96
    float* eins = b2s + 96;           // 64x5
    float* us   = eins + 320;         // 64x3
    int*   srcs = (int*)(us + 192);   // 64
    int*   dsts = srcs + 64;          // 64
    float* hT   = (float*)(dsts + 64);// [j=64][e padded to 68]  (16B aligned)
    float* hsh  = hT + 64*68;         // [e=64][96]

    int tid = threadIdx.x;
    for (int i = tid; i < 320;  i += 128) w1s[i] = W1[i];
    for (int i = tid; i < 64;   i += 128) b1s[i] = b1[i];
    for (int i = tid; i < 6144; i += 128) w2s[i] = W2[i];
    for (int i = tid; i < 96;   i += 128) b2s[i] = b2[i];

    const int ntiles = Ee / 64;
    for (int tile = blockIdx.x; tile < ntiles; tile += gridDim.x) {
        __syncthreads();   // covers weight loads (1st iter) and shared reuse (later iters)
        int e0 = tile * 64;
        for (int i = tid; i < 320; i += 128) eins[i] = g_edge_in[e0*5 + i];
        for (int i = tid; i < 192; i += 128) us[i]   = g_u[e0*3 + i];
        if (tid < 64) { srcs[tid] = g_src[e0 + tid]; dsts[tid] = g_dst[e0 + tid]; }
        __syncthreads();

        // hidden = elu(edge_in @ W1 + b1): thread = (e = tid&63, j = (tid>>6)+2i)
        {
            int e  = tid & 63;
            int j0 = tid >> 6;
            float x0 = eins[e*5+0], x1 = eins[e*5+1], x2 = eins[e*5+2];
            float x3 = eins[e*5+3], x4 = eins[e*5+4];
            #pragma unroll
            for (int i = 0; i < 32; i++) {
                int j = j0 + 2*i;
                float a = b1s[j] + x0*w1s[j] + x1*w1s[64+j] + x2*w1s[128+j]
                                 + x3*w1s[192+j] + x4*w1s[256+j];
                hT[j*68 + e] = elu1(a);
            }
        }
        __syncthreads();

        // h = hidden @ W2 + b2 : register-blocked GEMM, thread tile 8 edges x 6 outs
        {
            int eg = tid >> 4;   // 0..7
            int og = tid & 15;   // 0..15
            float acc[8][6];
            #pragma unroll
            for (int i = 0; i < 8; i++)
                #pragma unroll
                for (int jj = 0; jj < 6; jj++) acc[i][jj] = 0.f;
            #pragma unroll 2
            for (int k = 0; k < 64; k++) {
                float4 a0 = *(const float4*)&hT[k*68 + eg*8];
                float4 a1 = *(const float4*)&hT[k*68 + eg*8 + 4];
                float aa[8] = {a0.x,a0.y,a0.z,a0.w,a1.x,a1.y,a1.z,a1.w};
                float w[6];
                #pragma unroll
                for (int jj = 0; jj < 6; jj++) w[jj] = w2s[k*96 + og*6 + jj];
                #pragma unroll
                for (int i = 0; i < 8; i++)
                    #pragma unroll
                    for (int jj = 0; jj < 6; jj++) acc[i][jj] += aa[i]*w[jj];
            }
            #pragma unroll
            for (int i = 0; i < 8; i++)
                #pragma unroll
                for (int jj = 0; jj < 6; jj++)
                    hsh[(eg*8+i)*96 + og*6 + jj] = acc[i][jj] + b2s[og*6+jj];
        }
        __syncthreads();

        // messages + vectorized atomic scatter: 64 edges x 32 features
        for (int task = tid; task < 64*32; task += 128) {
            int e = task >> 5;
            int f = task & 31;
            float gs  = hsh[e*96 + f];
            float gv  = hsh[e*96 + 32 + f];
            float gsv = hsh[e*96 + 64 + f];
            int src = srcs[e], dst = dsts[e];
            float u0 = us[e*3+0], u1 = us[e*3+1], u2 = us[e*3+2];
            float ssrc = g_s[src*Ff + f];
            const float* vp = &g_v[(src*Ff + f)*3];
            float t = gsv * ssrc;
            float4 m = make_float4(gs*ssrc,
                                   gv*vp[0] + t*u0,
                                   gv*vp[1] + t*u1,
                                   gv*vp[2] + t*u2);
            atomicAdd(&g_acc[dst*Ff + f], m);   // sm_90+ vector RED.128
        }
    }
}

// ---------------- per-layer node update: residual s,v ----------------
__global__ void k_update(const float* __restrict__ Ws, const float* __restrict__ Wv) {
    __shared__ float  wss[1024], wvs[1024];
    __shared__ float4 msh[4][32];
    int tid = threadIdx.x;
    for (int i = tid; i < 1024; i += 128) { wss[i] = Ws[i]; wvs[i] = Wv[i]; }
    __syncthreads();
    int w = tid >> 5, lane = tid & 31;
    int node = blockIdx.x*4 + w;
    if (node >= Nn) return;
    float invd = g_invden[node];
    float4 a = g_acc[node*Ff + lane];
    msh[w][lane] = make_float4(a.x*invd, a.y*invd, a.z*invd, a.w*invd);
    __syncwarp();
    float so = 0.f, v0 = 0.f, v1 = 0.f, v2 = 0.f;
    #pragma unroll
    for (int f = 0; f < 32; f++) {
        float4 m = msh[w][f];
        float wsv = wss[f*32 + lane];
        float wvv = wvs[f*32 + lane];
        so += m.x*wsv;
        v0 += m.y*wvv; v1 += m.z*wvv; v2 += m.w*wvv;
    }
    g_s[node*Ff + lane] += elu1(so);
    float* vp = &g_v[(node*Ff + lane)*3];
    vp[0] += v0; vp[1] += v1; vp[2] += v2;
}

// ---------------- invariant map + graph pooling (atomic) ----------------
__global__ void k_inv(const float* __restrict__ W_inv, const float* __restrict__ b_inv,
                      const int* __restrict__ batch) {
    __shared__ float wi[64*128];
    __shared__ float bi[128];
    __shared__ float feat[4][64];
    int tid = threadIdx.x;
    for (int i = tid; i < 64*128; i += 128) wi[i] = W_inv[i];
    if (tid < 128) bi[tid] = b_inv[tid];
    __syncthreads();
    int w = tid >> 5, lane = tid & 31;
    int nwarps = gridDim.x*4;
    for (int node = blockIdx.x*4 + w; node < Nn; node += nwarps) {
        float sval = g_s[node*Ff + lane];
        const float* vp = &g_v[(node*Ff + lane)*3];
        float vn = sqrtf(vp[0]*vp[0] + vp[1]*vp[1] + vp[2]*vp[2] + EPSf);
        feat[w][lane]      = sval;
        feat[w][32 + lane] = vn;
        __syncwarp();
        int b = batch[node];
        #pragma unroll
        for (int r = 0; r < 4; r++) {
            int c = lane + 32*r;
            float acc = bi[c];
            #pragma unroll 8
            for (int k = 0; k < 64; k++) acc += feat[w][k] * wi[k*128 + c];
            atomicAdd(&g_xg[b*NINVc + c], acc);
        }
        __syncwarp();
    }
}

// ---------------- head: pool-finalize + BN1 stats ----------------
__global__ void k_pool_bn1() {
    __shared__ float ssum[256], ssq[256];
    int c = blockIdx.x, tid = threadIdx.x;
    float s = 0.f, q = 0.f;
    for (int g = tid; g < Gc; g += 256) {
        float val = g_xg[g*NINVc + c] / fmaxf(g_gcnt[g], 1.f);
        g_xgp[g*NINVc + c] = val;
        s += val; q += val*val;
    }
    ssum[tid] = s; ssq[tid] = q; __syncthreads();
    for (int st = 128; st > 0; st >>= 1) {
        if (tid < st) { ssum[tid] += ssum[tid+st]; ssq[tid] += ssq[tid+st]; }
        __syncthreads();
    }
    if (tid == 0) {
        float m = ssum[0] / (float)Gc;
        float var = ssq[0] / (float)Gc - m*m;
        g_mean1[c] = m;
        g_rstd1[c] = rsqrtf(var + 1e-5f);
    }
}
__global__ void k_fc1(const float* __restrict__ g1, const float* __restrict__ be1,
                      const float* __restrict__ Wf1, const float* __restrict__ bf1) {
    __shared__ float a[128];
    int g = blockIdx.x, j = threadIdx.x;
    float xv = g_xgp[g*NINVc + j];
    a[j] = elu1((xv - g_mean1[j]) * g_rstd1[j] * g1[j] + be1[j]);
    __syncthreads();
    float acc = bf1[j];
    #pragma unroll 8
    for (int k = 0; k < 128; k++) acc += a[k] * Wf1[k*128 + j];
    g_z1[g*NINVc + j] = acc;
}
__global__ void k_bn2() {
    __shared__ float ssum[256], ssq[256];
    int c = blockIdx.x, tid = threadIdx.x;
    float s = 0.f, q = 0.f;
    for (int g = tid; g < Gc; g += 256) {
        float val = g_z1[g*NINVc + c];
        s += val; q += val*val;
    }
    ssum[tid] = s; ssq[tid] = q; __syncthreads();
    for (int st = 128; st > 0; st >>= 1) {
        if (tid < st) { ssum[tid] += ssum[tid+st]; ssq[tid] += ssq[tid+st]; }
        __syncthreads();
    }
    if (tid == 0) {
        float m = ssum[0] / (float)Gc;
        float var = ssq[0] / (float)Gc - m*m;
        g_mean2[c] = m;
        g_rstd2[c] = rsqrtf(var + 1e-5f);
    }
}
__global__ void k_head(const float* __restrict__ g2, const float* __restrict__ be2,
                       const float* __restrict__ Wf2, const float* __restrict__ bf2,
                       float* __restrict__ out) {
    int w = threadIdx.x >> 5, lane = threadIdx.x & 31;
    int g = blockIdx.x*4 + w;
    if (g >= Gc) return;
    float p = 0.f;
    for (int k = lane; k < 128; k += 32) {
        float zv = g_z1[g*NINVc + k];
        float av = elu1((zv - g_mean2[k]) * g_rstd2[k] * g2[k] + be2[k]);
        p += av * Wf2[k];
    }
    #pragma unroll
    for (int off = 16; off; off >>= 1) p += __shfl_down_sync(0xffffffffu, p, off);
    if (lane == 0) out[g] = p + bf2[0];
}

// ---------------- launch ----------------
extern "C" void kernel_launch(void* const* d_in, const int* in_sizes, int n_in,
                              void* d_out, int out_size) {
    const float* x     = (const float*)d_in[0];
    const float* pos   = (const float*)d_in[1];
    const int*   ei    = (const int*)d_in[2];     // int32 (JAX x64 disabled)
    const float* eattr = (const float*)d_in[3];
    const int*   batch = (const int*)d_in[4];     // int32
    const float* W_es  = (const float*)d_in[5];
    const float* b_es  = (const float*)d_in[6];
    const float* W_ev  = (const float*)d_in[7];
    const float* W1    = (const float*)d_in[8];
    const float* b1    = (const float*)d_in[9];
    const float* W2    = (const float*)d_in[10];
    const float* b2    = (const float*)d_in[11];
    const float* Ws    = (const float*)d_in[12];
    const float* Wv    = (const float*)d_in[13];
    const float* W_inv = (const float*)d_in[14];
    const float* b_inv = (const float*)d_in[15];
    const float* g1    = (const float*)d_in[16];
    const float* be1   = (const float*)d_in[17];
    const float* Wf1   = (const float*)d_in[18];
    const float* bf1   = (const float*)d_in[19];
    const float* g2    = (const float*)d_in[20];
    const float* be2   = (const float*)d_in[21];
    const float* Wf2   = (const float*)d_in[22];
    const float* bf2   = (const float*)d_in[23];
    float* out = (float*)d_out;

    const int MSG_SMEM = MSG_SMEM_FLOATS * 4;
    cudaFuncSetAttribute(k_msg, cudaFuncAttributeMaxDynamicSharedMemorySize, MSG_SMEM);

    k_zero_node_graph<<<(Nn + Gc + Gc*NINVc + 255)/256, 256>>>();
    k_edge_prep<<<(Ee + 255)/256, 256>>>(pos, ei, eattr);
    k_gcnt<<<(Nn + 255)/256, 256>>>(batch);
    k_invden<<<(Nn + 255)/256, 256>>>();
    k_embed<<<(Nn*Ff + 255)/256, 256>>>(x, pos, W_es, b_es, W_ev);

    for (int l = 0; l < NLc; l++) {
        k_zero_acc<<<(Nn*Ff + 255)/256, 256>>>();
        k_msg<<<2048, 128, MSG_SMEM>>>(W1 + l*5*Hc, b1 + l*Hc,
                                       W2 + l*Hc*3*Ff, b2 + l*3*Ff);
        k_update<<<Nn/4, 128>>>(Ws + l*Ff*Ff, Wv + l*Ff*Ff);
    }

    k_inv<<<1024, 128>>>(W_inv, b_inv, batch);
    k_pool_bn1<<<NINVc, 256>>>();
    k_fc1<<<Gc, 128>>>(g1, be1, Wf1, bf1);
    k_bn2<<<NINVc, 256>>>();
    k_head<<<Gc/4, 128>>>(g2, be2, Wf2, bf2, out);
}

// round 3
// speedup vs baseline: 1.2082x; 1.2082x over previous
#include <cuda_runtime.h>
#include <math.h>

#define Nn   50000
#define Ee   800000
#define Ff   32
#define NINVc 128
#define NLc  4
#define Hc   64
#define Gc   2048
#define EPSf 1e-6f

typedef unsigned long long u64;

// ---------------- device scratch (no allocs allowed) ----------------
__device__ float  g_edge_in[Ee*5];
__device__ float  g_u[Ee*3];
__device__ int    g_src[Ee];
__device__ int    g_dst[Ee];
__device__ float  g_s[Nn*Ff];
__device__ float  g_v[Nn*Ff*3];
__device__ float4 g_acc[Nn*Ff];       // {ms, mv0, mv1, mv2} accumulators
__device__ float  g_invden[Nn];
__device__ float  g_cnt[Nn];
__device__ float  g_xg[Gc*NINVc];
__device__ float  g_gcnt[Gc];
__device__ float  g_xgp[Gc*NINVc];
__device__ float  g_z1[Gc*NINVc];
__device__ float  g_mean1[NINVc], g_rstd1[NINVc], g_mean2[NINVc], g_rstd2[NINVc];

__device__ __forceinline__ float elu1(float x) { return x > 0.f ? x : expm1f(x); }

// f32x2 packed-math helpers (FFMA2 — only reachable via PTX)
__device__ __forceinline__ u64 pack2(float lo, float hi) {
    u64 r; asm("mov.b64 %0, {%1,%2};" : "=l"(r) : "f"(lo), "f"(hi)); return r;
}
__device__ __forceinline__ void unpack2(float& lo, float& hi, u64 v) {
    asm("mov.b64 {%0,%1}, %2;" : "=f"(lo), "=f"(hi) : "l"(v));
}
__device__ __forceinline__ u64 fma2(u64 a, u64 b, u64 c) {
    u64 d; asm("fma.rn.f32x2 %0, %1, %2, %3;" : "=l"(d) : "l"(a), "l"(b), "l"(c)); return d;
}
__device__ __forceinline__ u64 add2(u64 a, u64 b) {
    u64 d; asm("add.rn.f32x2 %0, %1, %2;" : "=l"(d) : "l"(a), "l"(b)); return d;
}

// ---------------- combined zero kernel (launch #1) ----------------
__global__ void k_zero_all() {
    int i = blockIdx.x*blockDim.x + threadIdx.x;
    if (i < Nn*Ff) { g_acc[i] = make_float4(0.f,0.f,0.f,0.f); return; }
    i -= Nn*Ff;
    if (i < Nn) { g_cnt[i] = 0.f; return; }
    i -= Nn;
    if (i < Gc) { g_gcnt[i] = 0.f; return; }
    i -= Gc;
    if (i < Gc*NINVc) g_xg[i] = 0.f;
}

// ---------------- preprocessing ----------------
__global__ void k_edge_prep(const float* __restrict__ pos,
                            const int* __restrict__ ei,
                            const float* __restrict__ eattr) {
    int e = blockIdx.x*blockDim.x + threadIdx.x;
    if (e >= Ee) return;
    int src = ei[e];
    int dst = ei[Ee + e];
    float dx = pos[dst*3+0] - pos[src*3+0];
    float dy = pos[dst*3+1] - pos[src*3+1];
    float dz = pos[dst*3+2] - pos[src*3+2];
    float d  = sqrtf(dx*dx + dy*dy + dz*dz + EPSf);
    float inv = 1.0f/d;
    g_edge_in[e*5+0] = d;
    g_edge_in[e*5+1] = eattr[e*4+0];
    g_edge_in[e*5+2] = eattr[e*4+1];
    g_edge_in[e*5+3] = eattr[e*4+2];
    g_edge_in[e*5+4] = eattr[e*4+3];
    g_u[e*3+0] = dx*inv;
    g_u[e*3+1] = dy*inv;
    g_u[e*3+2] = dz*inv;
    g_src[e] = src;
    g_dst[e] = dst;
    atomicAdd(&g_cnt[dst], 1.f);
}
__global__ void k_gcnt(const int* __restrict__ batch) {
    int n = blockIdx.x*blockDim.x + threadIdx.x;
    if (n < Nn) atomicAdd(&g_gcnt[batch[n]], 1.f);
}
__global__ void k_invden() {
    int n = blockIdx.x*blockDim.x + threadIdx.x;
    if (n < Nn) g_invden[n] = 1.f / fmaxf(g_cnt[n], 1.f);
}

// ---------------- embedding ----------------
__global__ void k_embed(const float* __restrict__ x, const float* __restrict__ pos,
                        const float* __restrict__ W_es, const float* __restrict__ b_es,
                        const float* __restrict__ W_ev) {
    int idx = blockIdx.x*blockDim.x + threadIdx.x;
    if (idx >= Nn*Ff) return;
    int n = idx >> 5, f = idx & 31;
    const float* xr = x + n*5;
    float s = b_es[f], ev = 0.f;
    #pragma unroll
    for (int k = 0; k < 5; k++) {
        float xv = xr[k];
        s  += xv * W_es[k*Ff + f];
        ev += xv * W_ev[k*Ff + f];
    }
    g_s[idx] = s;
    float p0 = pos[n*3+0], p1 = pos[n*3+1], p2 = pos[n*3+2];
    g_v[idx*3+0] = ev*p0;
    g_v[idx*3+1] = ev*p1;
    g_v[idx*3+2] = ev*p2;
}

// ---------------- per-layer fused: edge MLP (f32x2 GEMM) + message + scatter ----------------
// shared (floats): w1s[320] b1s[64] w2s[6144] b2s[96] eins[320] us[192]
//                  srcs[64](int) dsts[64](int) hT[64*68]
#define MSG_SMEM_FLOATS (320+64+6144+96+320+192+64+64+64*68)
__global__ void __launch_bounds__(128, 4)
k_msg(const float* __restrict__ W1, const float* __restrict__ b1,
      const float* __restrict__ W2, const float* __restrict__ b2) {
    extern __shared__ float sm[];
    float* w1s  = sm;                 // 5x64
    float* b1s  = w1s + 320;          // 64
    float* w2s  = b1s + 64;           // 64x96
    float* b2s  = w2s + 6144;         // 96
    float* eins = b2s + 96;           // 64x5
    float* us   = eins + 320;         // 64x3
    int*   srcs = (int*)(us + 192);   // 64
    int*   dsts = srcs + 64;          // 64
    float* hT   = (float*)(dsts + 64);// [j=64][e padded to 68]

    int tid = threadIdx.x;
    for (int i = tid; i < 320;  i += 128) w1s[i] = W1[i];
    for (int i = tid; i < 64;   i += 128) b1s[i] = b1[i];
    for (int i = tid; i < 6144; i += 128) w2s[i] = W2[i];
    for (int i = tid; i < 96;   i += 128) b2s[i] = b2[i];

    const int ntiles = Ee / 64;
    for (int tile = blockIdx.x; tile < ntiles; tile += gridDim.x) {
        __syncthreads();   // weight loads (1st iter) / shared reuse (later)
        int e0 = tile * 64;
        for (int i = tid; i < 320; i += 128) eins[i] = g_edge_in[e0*5 + i];
        for (int i = tid; i < 192; i += 128) us[i]   = g_u[e0*3 + i];
        if (tid < 64) { srcs[tid] = g_src[e0 + tid]; dsts[tid] = g_dst[e0 + tid]; }
        __syncthreads();

        // MLP1: hidden = elu(edge_in @ W1 + b1). thread = (e = tid&63, 32 j's as 16 f32x2 pairs)
        {
            int e  = tid & 63;
            int j0 = (tid >> 6) * 32;
            float x0 = eins[e*5+0], x1 = eins[e*5+1], x2 = eins[e*5+2];
            float x3 = eins[e*5+3], x4 = eins[e*5+4];
            u64 xd[5] = { pack2(x0,x0), pack2(x1,x1), pack2(x2,x2), pack2(x3,x3), pack2(x4,x4) };
            #pragma unroll
            for (int i = 0; i < 16; i++) {
                int j = j0 + 2*i;
                u64 a = *(const u64*)&b1s[j];
                #pragma unroll
                for (int k = 0; k < 5; k++)
                    a = fma2(xd[k], *(const u64*)&w1s[k*64 + j], a);
                float lo, hi; unpack2(lo, hi, a);
                hT[j*68 + e]     = elu1(lo);
                hT[(j+1)*68 + e] = elu1(hi);
            }
        }
        __syncthreads();

        // GEMM2 (f32x2) fused with message + scatter.
        // thread tile: 8 edges (eg) x f-pair (og*2, og*2+1) across the 3 output groups.
        {
            int eg = tid >> 4;   // 0..7
            int og = tid & 15;   // 0..15
            int f0 = og * 2;
            u64 acc2[8][3];
            #pragma unroll
            for (int i = 0; i < 8; i++)
                #pragma unroll
                for (int g = 0; g < 3; g++) acc2[i][g] = 0ull;
            #pragma unroll 2
            for (int k = 0; k < 64; k++) {
                float4 a0 = *(const float4*)&hT[k*68 + eg*8];
                float4 a1 = *(const float4*)&hT[k*68 + eg*8 + 4];
                u64 ad[8] = { pack2(a0.x,a0.x), pack2(a0.y,a0.y), pack2(a0.z,a0.z), pack2(a0.w,a0.w),
                              pack2(a1.x,a1.x), pack2(a1.y,a1.y), pack2(a1.z,a1.z), pack2(a1.w,a1.w) };
                const float* wrow = &w2s[k*96 + f0];
                u64 w0 = *(const u64*)&wrow[0];
                u64 w1v = *(const u64*)&wrow[32];
                u64 w2v = *(const u64*)&wrow[64];
                #pragma unroll
                for (int i = 0; i < 8; i++) {
                    acc2[i][0] = fma2(ad[i], w0,  acc2[i][0]);
                    acc2[i][1] = fma2(ad[i], w1v, acc2[i][1]);
                    acc2[i][2] = fma2(ad[i], w2v, acc2[i][2]);
                }
            }
            u64 bb0 = *(const u64*)&b2s[f0];
            u64 bb1 = *(const u64*)&b2s[32 + f0];
            u64 bb2 = *(const u64*)&b2s[64 + f0];
            #pragma unroll
            for (int i = 0; i < 8; i++) {
                int e = eg*8 + i;
                float gsL,gsH, gvL,gvH, gtL,gtH;
                unpack2(gsL, gsH, add2(acc2[i][0], bb0));
                unpack2(gvL, gvH, add2(acc2[i][1], bb1));
                unpack2(gtL, gtH, add2(acc2[i][2], bb2));
                int src = srcs[e], dst = dsts[e];
                float u0 = us[e*3+0], u1 = us[e*3+1], u2 = us[e*3+2];
                float2 ss = *(const float2*)&g_s[src*Ff + f0];
                const float* vp = &g_v[(src*Ff + f0)*3];
                float2 va = *(const float2*)&vp[0];
                float2 vb = *(const float2*)&vp[2];
                float2 vc = *(const float2*)&vp[4];
                float tL = gtL * ss.x, tH = gtH * ss.y;
                float4 mL = make_float4(gsL*ss.x,
                                        gvL*va.x + tL*u0,
                                        gvL*va.y + tL*u1,
                                        gvL*vb.x + tL*u2);
                float4 mH = make_float4(gsH*ss.y,
                                        gvH*vb.y + tH*u0,
                                        gvH*vc.x + tH*u1,
                                        gvH*vc.y + tH*u2);
                atomicAdd(&g_acc[dst*Ff + f0],     mL);   // RED.128
                atomicAdd(&g_acc[dst*Ff + f0 + 1], mH);
            }
        }
    }
}

// ---------------- per-layer node update: residual s,v + acc reset ----------------
__global__ void k_update(const float* __restrict__ Ws, const float* __restrict__ Wv) {
    __shared__ float  wss[1024], wvs[1024];
    __shared__ float4 msh[4][32];
    int tid = threadIdx.x;
    for (int i = tid; i < 1024; i += 128) { wss[i] = Ws[i]; wvs[i] = Wv[i]; }
    __syncthreads();
    int w = tid >> 5, lane = tid & 31;
    int node = blockIdx.x*4 + w;
    if (node >= Nn) return;
    float invd = g_invden[node];
    float4 a = g_acc[node*Ff + lane];
    g_acc[node*Ff + lane] = make_float4(0.f,0.f,0.f,0.f);  // reset for next layer
    msh[w][lane] = make_float4(a.x*invd, a.y*invd, a.z*invd, a.w*invd);
    __syncwarp();
    float so = 0.f, v0 = 0.f, v1 = 0.f, v2 = 0.f;
    #pragma unroll
    for (int f = 0; f < 32; f++) {
        float4 m = msh[w][f];
        float wsv = wss[f*32 + lane];
        float wvv = wvs[f*32 + lane];
        so += m.x*wsv;
        v0 += m.y*wvv; v1 += m.z*wvv; v2 += m.w*wvv;
    }
    g_s[node*Ff + lane] += elu1(so);
    float* vp = &g_v[(node*Ff + lane)*3];
    vp[0] += v0; vp[1] += v1; vp[2] += v2;
}

// ---------------- invariant map + graph pooling (atomic) ----------------
__global__ void k_inv(const float* __restrict__ W_inv, const float* __restrict__ b_inv,
                      const int* __restrict__ batch) {
    __shared__ float wi[64*128];
    __shared__ float bi[128];
    __shared__ float feat[4][64];
    int tid = threadIdx.x;
    for (int i = tid; i < 64*128; i += 128) wi[i] = W_inv[i];
    if (tid < 128) bi[tid] = b_inv[tid];
    __syncthreads();
    int w = tid >> 5, lane = tid & 31;
    int nwarps = gridDim.x*4;
    for (int node = blockIdx.x*4 + w; node < Nn; node += nwarps) {
        float sval = g_s[node*Ff + lane];
        const float* vp = &g_v[(node*Ff + lane)*3];
        float vn = sqrtf(vp[0]*vp[0] + vp[1]*vp[1] + vp[2]*vp[2] + EPSf);
        feat[w][lane]      = sval;
        feat[w][32 + lane] = vn;
        __syncwarp();
        int b = batch[node];
        #pragma unroll
        for (int r = 0; r < 4; r++) {
            int c = lane + 32*r;
            float acc = bi[c];
            #pragma unroll 8
            for (int k = 0; k < 64; k++) acc += feat[w][k] * wi[k*128 + c];
            atomicAdd(&g_xg[b*NINVc + c], acc);
        }
        __syncwarp();
    }
}

// ---------------- head ----------------
__global__ void k_pool_bn1() {
    __shared__ float ssum[256], ssq[256];
    int c = blockIdx.x, tid = threadIdx.x;
    float s = 0.f, q = 0.f;
    for (int g = tid; g < Gc; g += 256) {
        float val = g_xg[g*NINVc + c] / fmaxf(g_gcnt[g], 1.f);
        g_xgp[g*NINVc + c] = val;
        s += val; q += val*val;
    }
    ssum[tid] = s; ssq[tid] = q; __syncthreads();
    for (int st = 128; st > 0; st >>= 1) {
        if (tid < st) { ssum[tid] += ssum[tid+st]; ssq[tid] += ssq[tid+st]; }
        __syncthreads();
    }
    if (tid == 0) {
        float m = ssum[0] / (float)Gc;
        float var = ssq[0] / (float)Gc - m*m;
        g_mean1[c] = m;
        g_rstd1[c] = rsqrtf(var + 1e-5f);
    }
}
__global__ void k_fc1(const float* __restrict__ g1, const float* __restrict__ be1,
                      const float* __restrict__ Wf1, const float* __restrict__ bf1) {
    __shared__ float a[128];
    int g = blockIdx.x, j = threadIdx.x;
    float xv = g_xgp[g*NINVc + j];
    a[j] = elu1((xv - g_mean1[j]) * g_rstd1[j] * g1[j] + be1[j]);
    __syncthreads();
    float acc = bf1[j];
    #pragma unroll 8
    for (int k = 0; k < 128; k++) acc += a[k] * Wf1[k*128 + j];
    g_z1[g*NINVc + j] = acc;
}
__global__ void k_bn2() {
    __shared__ float ssum[256], ssq[256];
    int c = blockIdx.x, tid = threadIdx.x;
    float s = 0.f, q = 0.f;
    for (int g = tid; g < Gc; g += 256) {
        float val = g_z1[g*NINVc + c];
        s += val; q += val*val;
    }
    ssum[tid] = s; ssq[tid] = q; __syncthreads();
    for (int st = 128; st > 0; st >>= 1) {
        if (tid < st) { ssum[tid] += ssum[tid+st]; ssq[tid] += ssq[tid+st]; }
        __syncthreads();
    }
    if (tid == 0) {
        float m = ssum[0] / (float)Gc;
        float var = ssq[0] / (float)Gc - m*m;
        g_mean2[c] = m;
        g_rstd2[c] = rsqrtf(var + 1e-5f);
    }
}
__global__ void k_head(const float* __restrict__ g2, const float* __restrict__ be2,
                       const float* __restrict__ Wf2, const float* __restrict__ bf2,
                       float* __restrict__ out) {
    int w = threadIdx.x >> 5, lane = threadIdx.x & 31;
    int g = blockIdx.x*4 + w;
    if (g >= Gc) return;
    float p = 0.f;
    for (int k = lane; k < 128; k += 32) {
        float zv = g_z1[g*NINVc + k];
        float av = elu1((zv - g_mean2[k]) * g_rstd2[k] * g2[k] + be2[k]);
        p += av * Wf2[k];
    }
    #pragma unroll
    for (int off = 16; off; off >>= 1) p += __shfl_down_sync(0xffffffffu, p, off);
    if (lane == 0) out[g] = p + bf2[0];
}

// ---------------- launch ----------------
extern "C" void kernel_launch(void* const* d_in, const int* in_sizes, int n_in,
                              void* d_out, int out_size) {
    const float* x     = (const float*)d_in[0];
    const float* pos   = (const float*)d_in[1];
    const int*   ei    = (const int*)d_in[2];     // int32 (JAX x64 disabled)
    const float* eattr = (const float*)d_in[3];
    const int*   batch = (const int*)d_in[4];     // int32
    const float* W_es  = (const float*)d_in[5];
    const float* b_es  = (const float*)d_in[6];
    const float* W_ev  = (const float*)d_in[7];
    const float* W1    = (const float*)d_in[8];
    const float* b1    = (const float*)d_in[9];
    const float* W2    = (const float*)d_in[10];
    const float* b2    = (const float*)d_in[11];
    const float* Ws    = (const float*)d_in[12];
    const float* Wv    = (const float*)d_in[13];
    const float* W_inv = (const float*)d_in[14];
    const float* b_inv = (const float*)d_in[15];
    const float* g1    = (const float*)d_in[16];
    const float* be1   = (const float*)d_in[17];
    const float* Wf1   = (const float*)d_in[18];
    const float* bf1   = (const float*)d_in[19];
    const float* g2    = (const float*)d_in[20];
    const float* be2   = (const float*)d_in[21];
    const float* Wf2   = (const float*)d_in[22];
    const float* bf2   = (const float*)d_in[23];
    float* out = (float*)d_out;

    const int MSG_SMEM = MSG_SMEM_FLOATS * 4;
    cudaFuncSetAttribute(k_msg, cudaFuncAttributeMaxDynamicSharedMemorySize, MSG_SMEM);

    int ztotal = Nn*Ff + Nn + Gc + Gc*NINVc;
    k_zero_all<<<(ztotal + 255)/256, 256>>>();                 // #1
    k_edge_prep<<<(Ee + 255)/256, 256>>>(pos, ei, eattr);      // #2
    k_gcnt<<<(Nn + 255)/256, 256>>>(batch);                    // #3
    k_invden<<<(Nn + 255)/256, 256>>>();                       // #4
    k_embed<<<(Nn*Ff + 255)/256, 256>>>(x, pos, W_es, b_es, W_ev);  // #5

    for (int l = 0; l < NLc; l++) {
        k_msg<<<2048, 128, MSG_SMEM>>>(W1 + l*5*Hc, b1 + l*Hc,      // #6 on first layer
                                       W2 + l*Hc*3*Ff, b2 + l*3*Ff);
        k_update<<<Nn/4, 128>>>(Ws + l*Ff*Ff, Wv + l*Ff*Ff);
    }

    k_inv<<<1024, 128>>>(W_inv, b_inv, batch);
    k_pool_bn1<<<NINVc, 256>>>();
    k_fc1<<<Gc, 128>>>(g1, be1, Wf1, bf1);
    k_bn2<<<NINVc, 256>>>();
    k_head<<<Gc/4, 128>>>(g2, be2, Wf2, bf2, out);
}